// round 14
// baseline (speedup 1.0000x reference)
#include <cuda_runtime.h>
#include <cuda_fp16.h>
#include <cstdint>

#define NB  4
#define NS  2048
#define ND  1024
#define NH  16
#define NDK 64
#define NTOK (NB * NS)   // 8192

// Scratch (static device globals: allocation-free per harness rules)
__device__ __half g_q[(size_t)NTOK * ND];    // (B,H,S,DK)  fp16, pre-scaled 1/8
__device__ __half g_k[(size_t)NTOK * ND];    // (B,H,S,DK)  fp16
__device__ __half g_v[(size_t)NTOK * ND];    // (B,H,DK,S)  transposed, fp16
__device__ __half g_ctx[(size_t)NTOK * ND];  // (B,S,D)     fp16
__device__ __half g_xr[(size_t)NTOK * ND];   // x rounded to fp16
__device__ __half g_wq[(size_t)ND * ND];
__device__ __half g_wk[(size_t)ND * ND];
__device__ __half g_wv[(size_t)ND * ND];
__device__ __half g_wo[(size_t)ND * ND];

// ---------------- helpers ----------------
__device__ __forceinline__ uint32_t smem_u32(const void* p) {
    uint32_t a;
    asm("{ .reg .u64 t; cvta.to.shared.u64 t, %1; cvt.u32.u64 %0, t; }" : "=r"(a) : "l"(p));
    return a;
}
__device__ __forceinline__ void cp16(uint32_t dst, const void* src) {
    asm volatile("cp.async.cg.shared.global [%0], [%1], 16;" :: "r"(dst), "l"(src));
}
#define CP_COMMIT() asm volatile("cp.async.commit_group;" ::: "memory")
#define CP_WAIT0()  asm volatile("cp.async.wait_group 0;" ::: "memory")
#define CP_WAIT1()  asm volatile("cp.async.wait_group 1;" ::: "memory")

__device__ __forceinline__ uint32_t packh2(float lo, float hi) {
    __half2 h = __floats2half2_rn(lo, hi);
    return *(uint32_t*)&h;
}
// 2^x on packed half2
__device__ __forceinline__ uint32_t ex2h2(uint32_t x) {
    uint32_t r;
    asm("ex2.approx.f16x2 %0, %1;" : "=r"(r) : "r"(x));
    return r;
}

// ldmatrix x4
__device__ __forceinline__ void ldsm4(uint32_t& r0, uint32_t& r1, uint32_t& r2, uint32_t& r3,
                                      uint32_t addr) {
    asm volatile("ldmatrix.sync.aligned.m8n8.x4.shared.b16 {%0,%1,%2,%3}, [%4];"
                 : "=r"(r0), "=r"(r1), "=r"(r2), "=r"(r3) : "r"(addr));
}

// D += A(m16 x k16, row) * B(k16 x n8, col), fp16 inputs, fp32 accum.
__device__ __forceinline__ void mma16(float* c, const uint32_t* a, const uint32_t* b) {
    asm volatile("mma.sync.aligned.m16n8k16.row.col.f32.f16.f16.f32 "
                 "{%0,%1,%2,%3}, {%4,%5,%6,%7}, {%8,%9}, {%0,%1,%2,%3};"
                 : "+f"(c[0]), "+f"(c[1]), "+f"(c[2]), "+f"(c[3])
                 : "r"(a[0]), "r"(a[1]), "r"(a[2]), "r"(a[3]),
                   "r"(b[0]), "r"(b[1]));
}

// =====================================================================
// Pre-pass: round fp32 -> fp16.
// =====================================================================
__global__ void round_f16_x(const float* __restrict__ src, __half* __restrict__ dst, int n4)
{
    int i = blockIdx.x * blockDim.x + threadIdx.x;
    if (i < n4) {
        float4 v = ((const float4*)src)[i];
        uint2 r;
        r.x = packh2(v.x, v.y);
        r.y = packh2(v.z, v.w);
        ((uint2*)dst)[i] = r;
    }
}

__global__ void round_f16_w(const float* __restrict__ s0, const float* __restrict__ s1,
                            const float* __restrict__ s2, const float* __restrict__ s3,
                            int n4)
{
    const int t = blockIdx.y;
    const float* src = (t == 0) ? s0 : (t == 1) ? s1 : (t == 2) ? s2 : s3;
    __half* dst = (t == 0) ? g_wq : (t == 1) ? g_wk : (t == 2) ? g_wv : g_wo;
    int i = blockIdx.x * blockDim.x + threadIdx.x;
    if (i < n4) {
        float4 v = ((const float4*)src)[i];
        uint2 r;
        r.x = packh2(v.x, v.y);
        r.y = packh2(v.z, v.w);
        ((uint2*)dst)[i] = r;
    }
}

// =====================================================================
// fp16 GEMM (NT) — unchanged from R13 (LDSM fragments, 3-stage cp.async).
// =====================================================================
#define LDA 20
#define GEMM_SMEM (3 * 2 * 128 * LDA * 4)   // 61440

template <int MODE>
__global__ __launch_bounds__(128, 2)
void gemm_f16(const __half* __restrict__ A,
              const __half* __restrict__ W0, const float* __restrict__ bia0,
              const __half* __restrict__ W1, const float* __restrict__ bia1,
              const __half* __restrict__ W2, const float* __restrict__ bia2,
              float* __restrict__ outp)
{
    extern __shared__ __align__(16) char dyn[];

    const __half *W, *Ain;
    const float* bias;
    __half* outh;
    const int z = (MODE == 1) ? blockIdx.z : 3;
    if (MODE == 1) {
        W    = (z == 0) ? W0   : (z == 1) ? W1   : W2;
        bias = (z == 0) ? bia0 : (z == 1) ? bia1 : bia2;
        outh = (z == 0) ? g_q  : (z == 1) ? g_k  : g_v;
        Ain  = A;
    } else {
        W = W0; bias = bia0; outh = nullptr; Ain = A;
    }

    const int tid  = threadIdx.x;
    const int warp = tid >> 5, lane = tid & 31;
    const int g = lane >> 2, tig = lane & 3;
    const int wm = warp >> 1, wn = warp & 1;
    const int m0 = blockIdx.y * 128, n0 = blockIdx.x * 128;

    const int q4 = lane >> 3, rr = lane & 7;
    const int arow = (q4 & 1) * 8 + rr, acol = (q4 >> 1) * 4;
    const int brow = (q4 >> 1) * 8 + rr, bcol = (q4 & 1) * 4;

    const uint32_t sbase = smem_u32(dyn);
    const int chr[4] = { (tid + 0) >> 2, (tid + 128) >> 2, (tid + 256) >> 2, (tid + 384) >> 2 };
    const int chc = (tid & 3) * 4;

    float acc[4][8][4];
    #pragma unroll
    for (int mf = 0; mf < 4; mf++)
        #pragma unroll
        for (int nf = 0; nf < 8; nf++)
            #pragma unroll
            for (int i = 0; i < 4; i++) acc[mf][nf][i] = 0.f;

    #pragma unroll
    for (int s = 0; s < 2; s++) {
        const int k0 = s * 32;
        #pragma unroll
        for (int i = 0; i < 4; i++) {
            cp16(sbase + (uint32_t)(s * 10240) + (uint32_t)(chr[i] * LDA + chc) * 4u,
                 Ain + (size_t)(m0 + chr[i]) * ND + k0 + chc * 2);
            cp16(sbase + 30720u + (uint32_t)(s * 10240) + (uint32_t)(chr[i] * LDA + chc) * 4u,
                 W   + (size_t)(n0 + chr[i]) * ND + k0 + chc * 2);
        }
        CP_COMMIT();
    }

    for (int it = 0; it < 32; it++) {
        const int cur = it % 3;
        if (it < 31) { CP_WAIT1(); } else { CP_WAIT0(); }
        __syncthreads();
        if (it < 30) {
            const int nxt = (it + 2) % 3;
            const int k0 = (it + 2) * 32;
            #pragma unroll
            for (int i = 0; i < 4; i++) {
                cp16(sbase + (uint32_t)(nxt * 10240) + (uint32_t)(chr[i] * LDA + chc) * 4u,
                     Ain + (size_t)(m0 + chr[i]) * ND + k0 + chc * 2);
                cp16(sbase + 30720u + (uint32_t)(nxt * 10240) + (uint32_t)(chr[i] * LDA + chc) * 4u,
                     W   + (size_t)(n0 + chr[i]) * ND + k0 + chc * 2);
            }
            CP_COMMIT();
        }

        const uint32_t asb = sbase + (uint32_t)(cur * 10240);
        const uint32_t bsb = sbase + 30720u + (uint32_t)(cur * 10240);
        #pragma unroll
        for (int kk = 0; kk < 2; kk++) {
            uint32_t af[4][4], bf[8][2];
            #pragma unroll
            for (int mf = 0; mf < 4; mf++)
                ldsm4(af[mf][0], af[mf][1], af[mf][2], af[mf][3],
                      asb + (uint32_t)(((wm * 64 + mf * 16 + arow) * LDA + kk * 8 + acol) * 4));
            #pragma unroll
            for (int j = 0; j < 4; j++)
                ldsm4(bf[2 * j][0], bf[2 * j][1], bf[2 * j + 1][0], bf[2 * j + 1][1],
                      bsb + (uint32_t)(((wn * 64 + j * 16 + brow) * LDA + kk * 8 + bcol) * 4));
            #pragma unroll
            for (int mf = 0; mf < 4; mf++)
                #pragma unroll
                for (int nf = 0; nf < 8; nf++)
                    mma16(acc[mf][nf], af[mf], bf[nf]);
        }
    }

    const float qs = (MODE == 1 && z == 0) ? 0.125f : 1.0f;
    #pragma unroll
    for (int mf = 0; mf < 4; mf++) {
        #pragma unroll
        for (int i2 = 0; i2 < 2; i2++) {
            const int m = m0 + wm * 64 + mf * 16 + g + i2 * 8;
            const int bb = m >> 11;
            const int s  = m & (NS - 1);
            #pragma unroll
            for (int nf = 0; nf < 8; nf++) {
                const int n = n0 + wn * 64 + nf * 8 + tig * 2;
                const float v0 = acc[mf][nf][i2 * 2 + 0] + bias[n];
                const float v1 = acc[mf][nf][i2 * 2 + 1] + bias[n + 1];
                if (MODE == 0) {
                    *(float2*)&outp[(size_t)m * ND + n] = make_float2(v0, v1);
                } else {
                    const int h = n >> 6, dk = n & 63;
                    if (z < 2) {
                        __half2 hv = __floats2half2_rn(v0 * qs, v1 * qs);
                        *(__half2*)&outh[(((size_t)(bb * NH + h)) * NS + s) * NDK + dk] = hv;
                    } else {
                        const size_t base = ((size_t)(bb * NH + h) * NDK + dk) * NS + s;
                        outh[base]      = __float2half_rn(v0);
                        outh[base + NS] = __float2half_rn(v1);
                    }
                }
            }
        }
    }
}

// =====================================================================
// fp16 flash attention v4: 512 threads, 16 warps x m16, kv tiles
// SOFTWARE-PIPELINED within each warp. Unnormalized exp makes kv tiles
// independent, so S(kt+1) mma executes between exp(kt) and PV(kt),
// covering the MUFU/shuffle chain with tensor work. 3-stage K/V ring
// (dynamic smem 55296 B), ping-pong S buffers via 2x-unrolled loop.
// =====================================================================
#define LDK 36
#define FLASH_MAT   (64 * LDK * 4)        // 9216 B per matrix
#define FLASH_STAGE (2 * FLASH_MAT)       // 18432 B (K + V)
#define FLASH_SMEM  (3 * FLASH_STAGE)     // 55296 B
#define L2E 1.4426950408889634f

__global__ __launch_bounds__(512)
void flash_f16()
{
    extern __shared__ __align__(16) uint32_t fdyn[];

    const int tid = threadIdx.x;
    const int w = tid >> 5, lane = tid & 31;     // 16 warps x m16
    const int g = lane >> 2, tig = lane & 3;
    const int bh = blockIdx.x;   // 0..63
    const int qt = blockIdx.y;   // 0..7

    const int sl = (lane & ~3) | tig;            // C->A shuffle source lane
    const int q4 = lane >> 3, rr = lane & 7;
    const int brow = (q4 >> 1) * 8 + rr, bcol = (q4 & 1) * 4;

    const __half* qb = g_q + (size_t)bh * NS * NDK + (size_t)qt * 256 * NDK;
    const __half* kb = g_k + (size_t)bh * NS * NDK;
    const __half* vb = g_v + (size_t)bh * NDK * NS;

    const uint32_t fbase = smem_u32(fdyn);
    const int frow = tid >> 3;                   // 512 thr: 1 chunk/matrix each
    const int fcw  = (tid & 7) * 4;

    // Q fragments: 4 k16 chunks over dk=64, rows w*16+{g,g+8}
    uint32_t Qa[4][4];
    {
        const uint32_t* q0 = (const uint32_t*)(qb + (size_t)(w * 16 + g) * NDK);
        const uint32_t* q1 = (const uint32_t*)(qb + (size_t)(w * 16 + g + 8) * NDK);
        #pragma unroll
        for (int kf = 0; kf < 4; kf++) {
            Qa[kf][0] = q0[kf * 8 + tig    ];
            Qa[kf][1] = q1[kf * 8 + tig    ];
            Qa[kf][2] = q0[kf * 8 + tig + 4];
            Qa[kf][3] = q1[kf * 8 + tig + 4];
        }
    }

    float O[8][4];
    #pragma unroll
    for (int nf = 0; nf < 8; nf++)
        #pragma unroll
        for (int i = 0; i < 4; i++) O[nf][i] = 0.f;
    float lr0 = 0.f, lr1 = 0.f;
    float Sa[8][4], Sb[8][4];

    auto prefetch = [&](int t, int st) {
        const uint32_t sb = fbase + (uint32_t)st * FLASH_STAGE;
        cp16(sb + (uint32_t)(frow * LDK + fcw) * 4u,
             kb + (size_t)(t * 64 + frow) * NDK + fcw * 2);
        cp16(sb + FLASH_MAT + (uint32_t)(frow * LDK + fcw) * 4u,
             vb + (size_t)frow * NS + t * 64 + fcw * 2);
    };

    auto s_mma = [&](float (&S)[8][4], uint32_t kbase) {
        #pragma unroll
        for (int nf = 0; nf < 8; nf++)
            #pragma unroll
            for (int i = 0; i < 4; i++) S[nf][i] = 0.f;
        #pragma unroll
        for (int kf = 0; kf < 4; kf++) {
            uint32_t b[8][2];
            #pragma unroll
            for (int j = 0; j < 4; j++)
                ldsm4(b[2 * j][0], b[2 * j][1], b[2 * j + 1][0], b[2 * j + 1][1],
                      kbase + (uint32_t)(((j * 16 + brow) * LDK + kf * 8 + bcol) * 4));
            #pragma unroll
            for (int nf = 0; nf < 8; nf++)
                mma16(S[nf], Qa[kf], b[nf]);
        }
    };

    auto body = [&](int kt, float (&Sc)[8][4], float (&Sn)[8][4]) {
        // protect stage (kt+2)%3 (last read as V(kt-1) in prev iteration)
        __syncthreads();
        if (kt <= 29) {
            prefetch(kt + 2, (kt + 2) % 3);
            CP_COMMIT();
            CP_WAIT1();     // tile kt+1 complete
        } else {
            CP_WAIT0();
        }
        __syncthreads();    // completed cp.async data visible block-wide

        // exp(kt): P = 2^(S*log2e) packed fp16 + fp32 row sums
        uint32_t P01[8], P23[8];
        {
            float s0 = 0.f, s1 = 0.f;
            #pragma unroll
            for (int nf = 0; nf < 8; nf++) {
                P01[nf] = ex2h2(packh2(Sc[nf][0] * L2E, Sc[nf][1] * L2E));
                P23[nf] = ex2h2(packh2(Sc[nf][2] * L2E, Sc[nf][3] * L2E));
                float2 f0 = __half22float2(*(__half2*)&P01[nf]);
                float2 f1 = __half22float2(*(__half2*)&P23[nf]);
                s0 += f0.x + f0.y;
                s1 += f1.x + f1.y;
            }
            s0 += __shfl_xor_sync(0xffffffffu, s0, 1);
            s0 += __shfl_xor_sync(0xffffffffu, s0, 2);
            s1 += __shfl_xor_sync(0xffffffffu, s1, 1);
            s1 += __shfl_xor_sync(0xffffffffu, s1, 2);
            lr0 += s0;
            lr1 += s1;
        }

        // S(kt+1) — independent tensor work covering the exp/shuffle chain
        if (kt <= 30)
            s_mma(Sn, fbase + (uint32_t)(((kt + 1) % 3) * FLASH_STAGE));

        // PV(kt): O += P @ V(kt)
        const uint32_t vbase = fbase + (uint32_t)((kt % 3) * FLASH_STAGE) + FLASH_MAT;
        #pragma unroll
        for (int kf = 0; kf < 4; kf++) {
            uint32_t a[4];
            a[0] = __shfl_sync(0xffffffffu, P01[2 * kf    ], sl);
            a[1] = __shfl_sync(0xffffffffu, P23[2 * kf    ], sl);
            a[2] = __shfl_sync(0xffffffffu, P01[2 * kf + 1], sl);
            a[3] = __shfl_sync(0xffffffffu, P23[2 * kf + 1], sl);
            uint32_t b[8][2];
            #pragma unroll
            for (int j = 0; j < 4; j++)
                ldsm4(b[2 * j][0], b[2 * j][1], b[2 * j + 1][0], b[2 * j + 1][1],
                      vbase + (uint32_t)(((j * 16 + brow) * LDK + kf * 8 + bcol) * 4));
            #pragma unroll
            for (int nf = 0; nf < 8; nf++)
                mma16(O[nf], a, b[nf]);
        }
    };

    // prologue: tiles 0,1 in flight; compute S(0)
    prefetch(0, 0); CP_COMMIT();
    prefetch(1, 1); CP_COMMIT();
    CP_WAIT1();          // tile 0 complete
    __syncthreads();
    s_mma(Sa, fbase);

    for (int k2 = 0; k2 < 16; k2++) {
        body(2 * k2,     Sa, Sb);
        body(2 * k2 + 1, Sb, Sa);
    }

    // normalize + store fp16 ctx (B,S,D)
    const int bb = bh >> 4, h = bh & 15;
    const float i0 = 1.0f / lr0, i1 = 1.0f / lr1;
    const int s0r = qt * 256 + w * 16 + g;
    const int s1r = s0r + 8;
    #pragma unroll
    for (int nf = 0; nf < 8; nf++) {
        const int col = h * 64 + nf * 8 + tig * 2;
        *(__half2*)&g_ctx[(size_t)(bb * NS + s0r) * ND + col] =
            __floats2half2_rn(O[nf][0] * i0, O[nf][1] * i0);
        *(__half2*)&g_ctx[(size_t)(bb * NS + s1r) * ND + col] =
            __floats2half2_rn(O[nf][2] * i1, O[nf][3] * i1);
    }
}

// =====================================================================
extern "C" void kernel_launch(void* const* d_in, const int* in_sizes, int n_in,
                              void* d_out, int out_size)
{
    const float* x  = (const float*)d_in[0];
    const float* Wq = (const float*)d_in[1];
    const float* bq = (const float*)d_in[2];
    const float* Wk = (const float*)d_in[3];
    const float* bk = (const float*)d_in[4];
    const float* Wv = (const float*)d_in[5];
    const float* bv = (const float*)d_in[6];
    const float* Wo = (const float*)d_in[7];
    const float* bo = (const float*)d_in[8];
    float* out = (float*)d_out;

    __half *xr, *wq, *wk, *wv, *wo, *cx;
    cudaGetSymbolAddress((void**)&xr, g_xr);
    cudaGetSymbolAddress((void**)&wq, g_wq);
    cudaGetSymbolAddress((void**)&wk, g_wk);
    cudaGetSymbolAddress((void**)&wv, g_wv);
    cudaGetSymbolAddress((void**)&wo, g_wo);
    cudaGetSymbolAddress((void**)&cx, g_ctx);

    cudaFuncSetAttribute(gemm_f16<1>, cudaFuncAttributeMaxDynamicSharedMemorySize, GEMM_SMEM);
    cudaFuncSetAttribute(gemm_f16<0>, cudaFuncAttributeMaxDynamicSharedMemorySize, GEMM_SMEM);
    cudaFuncSetAttribute(flash_f16,   cudaFuncAttributeMaxDynamicSharedMemorySize, FLASH_SMEM);

    const int nx4 = NTOK * ND / 4, nw4 = ND * ND / 4;
    round_f16_x<<<(nx4 + 255) / 256, 256>>>(x, xr, nx4);
    round_f16_w<<<dim3((nw4 + 255) / 256, 4), 256>>>(Wq, Wk, Wv, Wo, nw4);

    dim3 gqkv(ND / 128, NTOK / 128, 3);
    gemm_f16<1><<<gqkv, 128, GEMM_SMEM>>>(xr, wq, bq, wk, bk, wv, bv, nullptr);

    flash_f16<<<dim3(NB * NH, NS / 256), 512, FLASH_SMEM>>>();

    dim3 go(ND / 128, NTOK / 128, 1);
    gemm_f16<0><<<go, 128, GEMM_SMEM>>>(cx, wo, bo, nullptr, nullptr, nullptr, nullptr, out);
}

// round 15
// speedup vs baseline: 1.0486x; 1.0486x over previous
#include <cuda_runtime.h>
#include <cuda_fp16.h>
#include <cstdint>

#define NB  4
#define NS  2048
#define ND  1024
#define NH  16
#define NDK 64
#define NTOK (NB * NS)   // 8192

// Scratch (static device globals: allocation-free per harness rules)
__device__ __half g_q[(size_t)NTOK * ND];    // (B,H,S,DK)  fp16, pre-scaled 1/8
__device__ __half g_k[(size_t)NTOK * ND];    // (B,H,S,DK)  fp16
__device__ __half g_v[(size_t)NTOK * ND];    // (B,H,DK,S)  transposed, fp16
__device__ __half g_ctx[(size_t)NTOK * ND];  // (B,S,D)     fp16
__device__ __half g_xr[(size_t)NTOK * ND];   // x rounded to fp16
__device__ __half g_wq[(size_t)ND * ND];
__device__ __half g_wk[(size_t)ND * ND];
__device__ __half g_wv[(size_t)ND * ND];
__device__ __half g_wo[(size_t)ND * ND];

// ---------------- helpers ----------------
__device__ __forceinline__ uint32_t smem_u32(const void* p) {
    uint32_t a;
    asm("{ .reg .u64 t; cvta.to.shared.u64 t, %1; cvt.u32.u64 %0, t; }" : "=r"(a) : "l"(p));
    return a;
}
__device__ __forceinline__ void cp16(uint32_t dst, const void* src) {
    asm volatile("cp.async.cg.shared.global [%0], [%1], 16;" :: "r"(dst), "l"(src));
}
#define CP_COMMIT() asm volatile("cp.async.commit_group;" ::: "memory")
#define CP_WAIT0()  asm volatile("cp.async.wait_group 0;" ::: "memory")
#define CP_WAIT1()  asm volatile("cp.async.wait_group 1;" ::: "memory")

__device__ __forceinline__ uint32_t packh2(float lo, float hi) {
    __half2 h = __floats2half2_rn(lo, hi);
    return *(uint32_t*)&h;
}
// 2^x on packed half2
__device__ __forceinline__ uint32_t ex2h2(uint32_t x) {
    uint32_t r;
    asm("ex2.approx.f16x2 %0, %1;" : "=r"(r) : "r"(x));
    return r;
}

// ldmatrix x4
__device__ __forceinline__ void ldsm4(uint32_t& r0, uint32_t& r1, uint32_t& r2, uint32_t& r3,
                                      uint32_t addr) {
    asm volatile("ldmatrix.sync.aligned.m8n8.x4.shared.b16 {%0,%1,%2,%3}, [%4];"
                 : "=r"(r0), "=r"(r1), "=r"(r2), "=r"(r3) : "r"(addr));
}

// D += A(m16 x k16, row) * B(k16 x n8, col), fp16 inputs, fp32 accum.
__device__ __forceinline__ void mma16(float* c, const uint32_t* a, const uint32_t* b) {
    asm volatile("mma.sync.aligned.m16n8k16.row.col.f32.f16.f16.f32 "
                 "{%0,%1,%2,%3}, {%4,%5,%6,%7}, {%8,%9}, {%0,%1,%2,%3};"
                 : "+f"(c[0]), "+f"(c[1]), "+f"(c[2]), "+f"(c[3])
                 : "r"(a[0]), "r"(a[1]), "r"(a[2]), "r"(a[3]),
                   "r"(b[0]), "r"(b[1]));
}

// =====================================================================
// Pre-pass: round fp32 -> fp16.
// =====================================================================
__global__ void round_f16_x(const float* __restrict__ src, __half* __restrict__ dst, int n4)
{
    int i = blockIdx.x * blockDim.x + threadIdx.x;
    if (i < n4) {
        float4 v = ((const float4*)src)[i];
        uint2 r;
        r.x = packh2(v.x, v.y);
        r.y = packh2(v.z, v.w);
        ((uint2*)dst)[i] = r;
    }
}

__global__ void round_f16_w(const float* __restrict__ s0, const float* __restrict__ s1,
                            const float* __restrict__ s2, const float* __restrict__ s3,
                            int n4)
{
    const int t = blockIdx.y;
    const float* src = (t == 0) ? s0 : (t == 1) ? s1 : (t == 2) ? s2 : s3;
    __half* dst = (t == 0) ? g_wq : (t == 1) ? g_wk : (t == 2) ? g_wv : g_wo;
    int i = blockIdx.x * blockDim.x + threadIdx.x;
    if (i < n4) {
        float4 v = ((const float4*)src)[i];
        uint2 r;
        r.x = packh2(v.x, v.y);
        r.y = packh2(v.z, v.w);
        ((uint2*)dst)[i] = r;
    }
}

// =====================================================================
// fp16 GEMM (NT) — unchanged (LDSM fragments, 3-stage cp.async, 1 sync).
// =====================================================================
#define LDA 20
#define GEMM_SMEM (3 * 2 * 128 * LDA * 4)   // 61440

template <int MODE>
__global__ __launch_bounds__(128, 2)
void gemm_f16(const __half* __restrict__ A,
              const __half* __restrict__ W0, const float* __restrict__ bia0,
              const __half* __restrict__ W1, const float* __restrict__ bia1,
              const __half* __restrict__ W2, const float* __restrict__ bia2,
              float* __restrict__ outp)
{
    extern __shared__ __align__(16) char dyn[];

    const __half *W, *Ain;
    const float* bias;
    __half* outh;
    const int z = (MODE == 1) ? blockIdx.z : 3;
    if (MODE == 1) {
        W    = (z == 0) ? W0   : (z == 1) ? W1   : W2;
        bias = (z == 0) ? bia0 : (z == 1) ? bia1 : bia2;
        outh = (z == 0) ? g_q  : (z == 1) ? g_k  : g_v;
        Ain  = A;
    } else {
        W = W0; bias = bia0; outh = nullptr; Ain = A;
    }

    const int tid  = threadIdx.x;
    const int warp = tid >> 5, lane = tid & 31;
    const int g = lane >> 2, tig = lane & 3;
    const int wm = warp >> 1, wn = warp & 1;
    const int m0 = blockIdx.y * 128, n0 = blockIdx.x * 128;

    const int q4 = lane >> 3, rr = lane & 7;
    const int arow = (q4 & 1) * 8 + rr, acol = (q4 >> 1) * 4;
    const int brow = (q4 >> 1) * 8 + rr, bcol = (q4 & 1) * 4;

    const uint32_t sbase = smem_u32(dyn);
    const int chr[4] = { (tid + 0) >> 2, (tid + 128) >> 2, (tid + 256) >> 2, (tid + 384) >> 2 };
    const int chc = (tid & 3) * 4;

    float acc[4][8][4];
    #pragma unroll
    for (int mf = 0; mf < 4; mf++)
        #pragma unroll
        for (int nf = 0; nf < 8; nf++)
            #pragma unroll
            for (int i = 0; i < 4; i++) acc[mf][nf][i] = 0.f;

    #pragma unroll
    for (int s = 0; s < 2; s++) {
        const int k0 = s * 32;
        #pragma unroll
        for (int i = 0; i < 4; i++) {
            cp16(sbase + (uint32_t)(s * 10240) + (uint32_t)(chr[i] * LDA + chc) * 4u,
                 Ain + (size_t)(m0 + chr[i]) * ND + k0 + chc * 2);
            cp16(sbase + 30720u + (uint32_t)(s * 10240) + (uint32_t)(chr[i] * LDA + chc) * 4u,
                 W   + (size_t)(n0 + chr[i]) * ND + k0 + chc * 2);
        }
        CP_COMMIT();
    }

    for (int it = 0; it < 32; it++) {
        const int cur = it % 3;
        if (it < 31) { CP_WAIT1(); } else { CP_WAIT0(); }
        __syncthreads();
        if (it < 30) {
            const int nxt = (it + 2) % 3;
            const int k0 = (it + 2) * 32;
            #pragma unroll
            for (int i = 0; i < 4; i++) {
                cp16(sbase + (uint32_t)(nxt * 10240) + (uint32_t)(chr[i] * LDA + chc) * 4u,
                     Ain + (size_t)(m0 + chr[i]) * ND + k0 + chc * 2);
                cp16(sbase + 30720u + (uint32_t)(nxt * 10240) + (uint32_t)(chr[i] * LDA + chc) * 4u,
                     W   + (size_t)(n0 + chr[i]) * ND + k0 + chc * 2);
            }
            CP_COMMIT();
        }

        const uint32_t asb = sbase + (uint32_t)(cur * 10240);
        const uint32_t bsb = sbase + 30720u + (uint32_t)(cur * 10240);
        #pragma unroll
        for (int kk = 0; kk < 2; kk++) {
            uint32_t af[4][4], bf[8][2];
            #pragma unroll
            for (int mf = 0; mf < 4; mf++)
                ldsm4(af[mf][0], af[mf][1], af[mf][2], af[mf][3],
                      asb + (uint32_t)(((wm * 64 + mf * 16 + arow) * LDA + kk * 8 + acol) * 4));
            #pragma unroll
            for (int j = 0; j < 4; j++)
                ldsm4(bf[2 * j][0], bf[2 * j][1], bf[2 * j + 1][0], bf[2 * j + 1][1],
                      bsb + (uint32_t)(((wn * 64 + j * 16 + brow) * LDA + kk * 8 + bcol) * 4));
            #pragma unroll
            for (int mf = 0; mf < 4; mf++)
                #pragma unroll
                for (int nf = 0; nf < 8; nf++)
                    mma16(acc[mf][nf], af[mf], bf[nf]);
        }
    }

    const float qs = (MODE == 1 && z == 0) ? 0.125f : 1.0f;
    #pragma unroll
    for (int mf = 0; mf < 4; mf++) {
        #pragma unroll
        for (int i2 = 0; i2 < 2; i2++) {
            const int m = m0 + wm * 64 + mf * 16 + g + i2 * 8;
            const int bb = m >> 11;
            const int s  = m & (NS - 1);
            #pragma unroll
            for (int nf = 0; nf < 8; nf++) {
                const int n = n0 + wn * 64 + nf * 8 + tig * 2;
                const float v0 = acc[mf][nf][i2 * 2 + 0] + bias[n];
                const float v1 = acc[mf][nf][i2 * 2 + 1] + bias[n + 1];
                if (MODE == 0) {
                    *(float2*)&outp[(size_t)m * ND + n] = make_float2(v0, v1);
                } else {
                    const int h = n >> 6, dk = n & 63;
                    if (z < 2) {
                        __half2 hv = __floats2half2_rn(v0 * qs, v1 * qs);
                        *(__half2*)&outh[(((size_t)(bb * NH + h)) * NS + s) * NDK + dk] = hv;
                    } else {
                        const size_t base = ((size_t)(bb * NH + h) * NDK + dk) * NS + s;
                        outh[base]      = __float2half_rn(v0);
                        outh[base + NS] = __float2half_rn(v1);
                    }
                }
            }
        }
    }
}

// =====================================================================
// fp16 flash attention v5 = R12 winner (256 thr, 8 warps x m32) with a
// 3-stage K/V ring and ONE __syncthreads per kt (prefetch target
// (kt+2)%3 == (kt-1)%3 was last read before this iteration's barrier).
// Unnormalized exp (ex2.approx.f16x2), P via shuffles, LDSM fragments.
// Dynamic smem: 3 x 18432 = 55296 B.
// =====================================================================
#define LDK 36
#define FLASH_MAT   (64 * LDK * 4)        // 9216 B per matrix
#define FLASH_STAGE (2 * FLASH_MAT)       // 18432 B (K + V)
#define FLASH_SMEM  (3 * FLASH_STAGE)     // 55296 B
#define L2E 1.4426950408889634f

__global__ __launch_bounds__(256)
void flash_f16()
{
    extern __shared__ __align__(16) uint32_t fdyn[];

    const int tid = threadIdx.x;
    const int w = tid >> 5, lane = tid & 31;
    const int g = lane >> 2, tig = lane & 3;
    const int bh = blockIdx.x;   // 0..63
    const int qt = blockIdx.y;   // 0..7

    const int sl = (lane & ~3) | tig;   // C->A shuffle source lane
    const int q4 = lane >> 3, rr = lane & 7;
    const int brow = (q4 >> 1) * 8 + rr, bcol = (q4 & 1) * 4;

    const __half* qb = g_q + (size_t)bh * NS * NDK + (size_t)qt * 256 * NDK;
    const __half* kb = g_k + (size_t)bh * NS * NDK;
    const __half* vb = g_v + (size_t)bh * NDK * NS;

    const uint32_t fbase = smem_u32(fdyn);
    // fill mapping: 64 rows x 8 chunks (16B) per matrix; 2 chunks/thread
    const int frow[2] = { tid >> 3, (tid + 256) >> 3 };
    const int fcw = (tid & 7) * 4;

    // Q fragments: 4 k16 chunks over dk=64, 2 m-tiles per warp
    uint32_t Qa[2][4][4];
    #pragma unroll
    for (int mf = 0; mf < 2; mf++) {
        const uint32_t* q0 = (const uint32_t*)(qb + (size_t)(w * 32 + mf * 16 + g) * NDK);
        const uint32_t* q1 = (const uint32_t*)(qb + (size_t)(w * 32 + mf * 16 + g + 8) * NDK);
        #pragma unroll
        for (int kf = 0; kf < 4; kf++) {
            Qa[mf][kf][0] = q0[kf * 8 + tig    ];
            Qa[mf][kf][1] = q1[kf * 8 + tig    ];
            Qa[mf][kf][2] = q0[kf * 8 + tig + 4];
            Qa[mf][kf][3] = q1[kf * 8 + tig + 4];
        }
    }

    float O[2][8][4];
    #pragma unroll
    for (int mf = 0; mf < 2; mf++)
        #pragma unroll
        for (int nf = 0; nf < 8; nf++)
            #pragma unroll
            for (int i = 0; i < 4; i++) O[mf][nf][i] = 0.f;
    float lr[2][2];
    lr[0][0] = lr[0][1] = lr[1][0] = lr[1][1] = 0.f;

    // prologue: tiles 0,1 -> stages 0,1
    #pragma unroll
    for (int t = 0; t < 2; t++) {
        const uint32_t sb = fbase + (uint32_t)(t * FLASH_STAGE);
        #pragma unroll
        for (int i = 0; i < 2; i++) {
            cp16(sb + (uint32_t)(frow[i] * LDK + fcw) * 4u,
                 kb + (size_t)(t * 64 + frow[i]) * NDK + fcw * 2);
            cp16(sb + FLASH_MAT + (uint32_t)(frow[i] * LDK + fcw) * 4u,
                 vb + (size_t)frow[i] * NS + t * 64 + fcw * 2);
        }
        CP_COMMIT();
    }

    for (int kt = 0; kt < NS / 64; kt++) {
        if (kt < 31) { CP_WAIT1(); } else { CP_WAIT0(); }
        __syncthreads();   // tile kt visible; stage (kt-1)%3 free for overwrite

        // prefetch tile kt+2 into stage (kt+2)%3  (== (kt-1)%3)
        if (kt < 30) {
            const uint32_t sb = fbase + (uint32_t)(((kt + 2) % 3) * FLASH_STAGE);
            #pragma unroll
            for (int i = 0; i < 2; i++) {
                cp16(sb + (uint32_t)(frow[i] * LDK + fcw) * 4u,
                     kb + (size_t)((kt + 2) * 64 + frow[i]) * NDK + fcw * 2);
                cp16(sb + FLASH_MAT + (uint32_t)(frow[i] * LDK + fcw) * 4u,
                     vb + (size_t)frow[i] * NS + (kt + 2) * 64 + fcw * 2);
            }
            CP_COMMIT();
        }

        const uint32_t kbase = fbase + (uint32_t)((kt % 3) * FLASH_STAGE);
        const uint32_t vbase = kbase + FLASH_MAT;

        // S = Q @ K^T (m32 x n64 per warp); B frags shared across mf
        float S[2][8][4];
        #pragma unroll
        for (int mf = 0; mf < 2; mf++)
            #pragma unroll
            for (int nf = 0; nf < 8; nf++)
                #pragma unroll
                for (int i = 0; i < 4; i++) S[mf][nf][i] = 0.f;
        #pragma unroll
        for (int kf = 0; kf < 4; kf++) {
            uint32_t b[8][2];
            #pragma unroll
            for (int j = 0; j < 4; j++)
                ldsm4(b[2 * j][0], b[2 * j][1], b[2 * j + 1][0], b[2 * j + 1][1],
                      kbase + (uint32_t)(((j * 16 + brow) * LDK + kf * 8 + bcol) * 4));
            #pragma unroll
            for (int nf = 0; nf < 8; nf++) {
                mma16(S[0][nf], Qa[0][kf], b[nf]);
                mma16(S[1][nf], Qa[1][kf], b[nf]);
            }
        }

        // P = 2^(S*log2e) packed fp16; fp32 row sums
        uint32_t P01[2][8], P23[2][8];
        #pragma unroll
        for (int mf = 0; mf < 2; mf++) {
            float s0 = 0.f, s1 = 0.f;
            #pragma unroll
            for (int nf = 0; nf < 8; nf++) {
                P01[mf][nf] = ex2h2(packh2(S[mf][nf][0] * L2E, S[mf][nf][1] * L2E));
                P23[mf][nf] = ex2h2(packh2(S[mf][nf][2] * L2E, S[mf][nf][3] * L2E));
                float2 f0 = __half22float2(*(__half2*)&P01[mf][nf]);
                float2 f1 = __half22float2(*(__half2*)&P23[mf][nf]);
                s0 += f0.x + f0.y;
                s1 += f1.x + f1.y;
            }
            s0 += __shfl_xor_sync(0xffffffffu, s0, 1);
            s0 += __shfl_xor_sync(0xffffffffu, s0, 2);
            s1 += __shfl_xor_sync(0xffffffffu, s1, 1);
            s1 += __shfl_xor_sync(0xffffffffu, s1, 2);
            lr[mf][0] += s0;
            lr[mf][1] += s1;
        }

        // O += P @ V
        #pragma unroll
        for (int kf = 0; kf < 4; kf++) {
            uint32_t a[2][4];
            #pragma unroll
            for (int mf = 0; mf < 2; mf++) {
                a[mf][0] = __shfl_sync(0xffffffffu, P01[mf][2 * kf    ], sl);
                a[mf][1] = __shfl_sync(0xffffffffu, P23[mf][2 * kf    ], sl);
                a[mf][2] = __shfl_sync(0xffffffffu, P01[mf][2 * kf + 1], sl);
                a[mf][3] = __shfl_sync(0xffffffffu, P23[mf][2 * kf + 1], sl);
            }
            uint32_t b[8][2];
            #pragma unroll
            for (int j = 0; j < 4; j++)
                ldsm4(b[2 * j][0], b[2 * j][1], b[2 * j + 1][0], b[2 * j + 1][1],
                      vbase + (uint32_t)(((j * 16 + brow) * LDK + kf * 8 + bcol) * 4));
            #pragma unroll
            for (int nf = 0; nf < 8; nf++) {
                mma16(O[0][nf], a[0], b[nf]);
                mma16(O[1][nf], a[1], b[nf]);
            }
        }
    }

    // normalize + store fp16 ctx (B,S,D)
    const int bb = bh >> 4, h = bh & 15;
    #pragma unroll
    for (int mf = 0; mf < 2; mf++) {
        const float i0 = 1.0f / lr[mf][0], i1 = 1.0f / lr[mf][1];
        const int s0r = qt * 256 + w * 32 + mf * 16 + g;
        const int s1r = s0r + 8;
        #pragma unroll
        for (int nf = 0; nf < 8; nf++) {
            const int col = h * 64 + nf * 8 + tig * 2;
            *(__half2*)&g_ctx[(size_t)(bb * NS + s0r) * ND + col] =
                __floats2half2_rn(O[mf][nf][0] * i0, O[mf][nf][1] * i0);
            *(__half2*)&g_ctx[(size_t)(bb * NS + s1r) * ND + col] =
                __floats2half2_rn(O[mf][nf][2] * i1, O[mf][nf][3] * i1);
        }
    }
}

// =====================================================================
extern "C" void kernel_launch(void* const* d_in, const int* in_sizes, int n_in,
                              void* d_out, int out_size)
{
    const float* x  = (const float*)d_in[0];
    const float* Wq = (const float*)d_in[1];
    const float* bq = (const float*)d_in[2];
    const float* Wk = (const float*)d_in[3];
    const float* bk = (const float*)d_in[4];
    const float* Wv = (const float*)d_in[5];
    const float* bv = (const float*)d_in[6];
    const float* Wo = (const float*)d_in[7];
    const float* bo = (const float*)d_in[8];
    float* out = (float*)d_out;

    __half *xr, *wq, *wk, *wv, *wo, *cx;
    cudaGetSymbolAddress((void**)&xr, g_xr);
    cudaGetSymbolAddress((void**)&wq, g_wq);
    cudaGetSymbolAddress((void**)&wk, g_wk);
    cudaGetSymbolAddress((void**)&wv, g_wv);
    cudaGetSymbolAddress((void**)&wo, g_wo);
    cudaGetSymbolAddress((void**)&cx, g_ctx);

    cudaFuncSetAttribute(gemm_f16<1>, cudaFuncAttributeMaxDynamicSharedMemorySize, GEMM_SMEM);
    cudaFuncSetAttribute(gemm_f16<0>, cudaFuncAttributeMaxDynamicSharedMemorySize, GEMM_SMEM);
    cudaFuncSetAttribute(flash_f16,   cudaFuncAttributeMaxDynamicSharedMemorySize, FLASH_SMEM);

    const int nx4 = NTOK * ND / 4, nw4 = ND * ND / 4;
    round_f16_x<<<(nx4 + 255) / 256, 256>>>(x, xr, nx4);
    round_f16_w<<<dim3((nw4 + 255) / 256, 4), 256>>>(Wq, Wk, Wv, Wo, nw4);

    dim3 gqkv(ND / 128, NTOK / 128, 3);
    gemm_f16<1><<<gqkv, 128, GEMM_SMEM>>>(xr, wq, bq, wk, bk, wv, bv, nullptr);

    flash_f16<<<dim3(NB * NH, NS / 256), 256, FLASH_SMEM>>>();

    dim3 go(ND / 128, NTOK / 128, 1);
    gemm_f16<0><<<go, 128, GEMM_SMEM>>>(cx, wo, bo, nullptr, nullptr, nullptr, nullptr, out);
}